// round 16
// baseline (speedup 1.0000x reference)
#include <cuda_runtime.h>
#include <cuda_fp16.h>
#include <cstdint>

// DynamicPointConvBackBone via mma.sync (base-ISA HMMA; tcgen05 unavailable on
// the harness's compute_103 PTX target).
// Resample-first: only B*K rows computed. GEMM [8192 x 1728] @ [1728 x 128]
// in single-pass fp16 (W pre-scaled by 2^14; unscaled before LN), fp32 accum.
// LayerNorm(eps=1e-3)+ReLU epilogue + coords output.
// R15 = R8 (best, 30.8us) micro-tuned:
//   * stage = 2 chunks (128 k) per double-buffer slot -> 14 barriers not 27
//   * prep_w vectorized (8 elem/thread) to cut the serial prep head
//   * odd-K3 tail: A second half zeroed (products vanish; B slot 27 is zero)

#define TILE_M 32
#define NTH    256
#define IDXP   28
#define MAXCH  28
#define CHUNK  64        // = Cin
#define ATB    8192      // A stage bytes (32 rows x 128 fp16 x 2B)
#define BTB    32768     // B stage bytes (128 k x 128 n x 2B)
#define WSCALE 16384.0f
#define WINV   (1.0f / 16384.0f)

// dynamic smem layout
#define SM_A   0                              // 2 x 8192
#define SM_B   (SM_A + 2 * ATB)               // 16384, 2 x 32768
#define SM_IDX (SM_B + 2 * BTB)               // 81920
#define SM_SRC (SM_IDX + TILE_M * IDXP * 4)   // 85504
#define SM_VAL (SM_SRC + TILE_M * 4)          // 85632
#define SM_RED (SM_VAL + 32)                  // 85664 (32 rows x 8 floats)
#define SM_GB  (SM_RED + TILE_M * 8 * 4)      // 86688 (gamma 128 + beta 128)
#define SM_TOTAL (SM_GB + 256 * 4)            // 87712

__device__ __align__(16) __half g_w[MAXCH * CHUNK * 128];   // [k][n] fp16, x2^14
                                                            // slot 27 stays zero

static __device__ __forceinline__ uint32_t smem_u32(const void* p) {
    uint32_t a;
    asm("{ .reg .u64 t; cvta.to.shared.u64 t, %1; cvt.u32.u64 %0, t; }" : "=r"(a) : "l"(p));
    return a;
}
static __device__ __forceinline__ uint32_t pack_h2(float lo, float hi) {
    uint32_t r;
    asm("cvt.rn.f16x2.f32 %0, %1, %2;" : "=r"(r) : "f"(hi), "f"(lo));
    return r;
}
static __device__ __forceinline__ void cpasync16(uint32_t dst, const void* src) {
    asm volatile("cp.async.cg.shared.global [%0], [%1], 16;" :: "r"(dst), "l"(src) : "memory");
}
static __device__ __forceinline__ void cpwait_all() {
    asm volatile("cp.async.wait_all;" ::: "memory");
}
static __device__ __forceinline__ void ldsm4(uint32_t* r, uint32_t addr) {
    asm volatile("ldmatrix.sync.aligned.m8n8.x4.shared.b16 {%0,%1,%2,%3}, [%4];"
                 : "=r"(r[0]), "=r"(r[1]), "=r"(r[2]), "=r"(r[3]) : "r"(addr));
}
static __device__ __forceinline__ void ldsm4t(uint32_t* r, uint32_t addr) {
    asm volatile("ldmatrix.sync.aligned.m8n8.x4.trans.shared.b16 {%0,%1,%2,%3}, [%4];"
                 : "=r"(r[0]), "=r"(r[1]), "=r"(r[2]), "=r"(r[3]) : "r"(addr));
}
static __device__ __forceinline__ void mma16816(float* d, const uint32_t* a,
                                                uint32_t b0, uint32_t b1) {
    asm volatile(
        "mma.sync.aligned.m16n8k16.row.col.f32.f16.f16.f32 "
        "{%0,%1,%2,%3}, {%4,%5,%6,%7}, {%8,%9}, {%0,%1,%2,%3};"
        : "+f"(d[0]), "+f"(d[1]), "+f"(d[2]), "+f"(d[3])
        : "r"(a[0]), "r"(a[1]), "r"(a[2]), "r"(a[3]), "r"(b0), "r"(b1));
}

// ---------------- prep: W -> fp16 x2^14, [k][n], 8 elems/thread ----------------
__global__ void prep_w(const float* __restrict__ W, int total8) {
    int t = blockIdx.x * blockDim.x + threadIdx.x;
    if (t >= total8) return;
    float4 v0 = __ldg((const float4*)W + 2 * t);
    float4 v1 = __ldg((const float4*)W + 2 * t + 1);
    uint4 h;
    h.x = pack_h2(v0.x * WSCALE, v0.y * WSCALE);
    h.y = pack_h2(v0.z * WSCALE, v0.w * WSCALE);
    h.z = pack_h2(v1.x * WSCALE, v1.y * WSCALE);
    h.w = pack_h2(v1.z * WSCALE, v1.w * WSCALE);
    ((uint4*)g_w)[t] = h;
}

// ---------------- main fused kernel ----------------
__global__ __launch_bounds__(NTH, 2)
void fused_mma_kernel(
    const float* __restrict__ feat,   // [N, 64]
    const float* __restrict__ coors,  // [M, 3]
    const int*   __restrict__ vidx,   // [M, K3]
    const int*   __restrict__ nums,   // [B]
    const float* __restrict__ gamma,  // [128]
    const float* __restrict__ beta,   // [128]
    float* __restrict__ out_feat,     // [rows_total, 128]
    float* __restrict__ out_coor,     // [rows_total, 4]
    int N, int M, int K3, int B, int K, int rows_total)
{
    extern __shared__ __align__(128) char sm[];
    const uint32_t smb = smem_u32(sm);
    const int tid  = threadIdx.x;
    const int wid  = tid >> 5;
    const int lane = tid & 31;
    const int row0 = blockIdx.x * TILE_M;

    int* s_idx = (int*)(sm + SM_IDX);
    int* s_src = (int*)(sm + SM_SRC);
    unsigned char* s_val = (unsigned char*)(sm + SM_VAL);
    float* s_red = (float*)(sm + SM_RED);
    float* s_gb  = (float*)(sm + SM_GB);

    // per-row source & validity
    if (tid < TILE_M) {
        int r = row0 + tid;
        int src = 0; bool valid = false;
        if (r < rows_total) {
            int b = r / K;
            int j = r - b * K;
            int off = 0;
            for (int i = 0; i < b; ++i) off += nums[i];
            valid = j < min(nums[b], K);
            src   = max(0, min(off + j, M - 1));
        }
        s_src[tid] = src;
        s_val[tid] = valid ? 1 : 0;
    }
    if (tid >= 128) {
        s_gb[tid - 128] = gamma[tid - 128];
        s_gb[tid]       = beta[tid - 128];
    }
    __syncthreads();

    // neighbor indices (pad cc >= K3 with -1 so the odd-K3 tail gathers zeros)
    for (int i = tid; i < TILE_M * IDXP; i += NTH) {
        int rr = i / IDXP, cc = i - rr * IDXP;
        int iv = -1;
        if (cc < K3) {
            int v = vidx[(long long)s_src[rr] * K3 + cc];
            iv = (v < 0) ? -1 : min(v, N - 1);
        }
        s_idx[i] = iv;
    }
    __syncthreads();

    const int stages = (K3 + 1) >> 1;     // 14 for K3=27

    // -------- loaders --------
    const int arow = tid >> 3;          // gather row 0..31
    const int aseg = tid & 7;           // 32B segment of 256B fp32 feature row
    float4 pa[4];                       // [chunk0: 0..1][chunk1: 2..3]

    auto a_issue = [&](int s) {
        const int c0 = 2 * s, c1 = 2 * s + 1;
        int gi0 = s_idx[arow * IDXP + c0];
        int gi1 = s_idx[arow * IDXP + c1];   // -1 beyond K3 (padded)
        if (gi0 >= 0) {
            const float4* src = (const float4*)(feat + (size_t)gi0 * CHUNK) + aseg * 2;
            pa[0] = __ldg(src + 0); pa[1] = __ldg(src + 1);
        } else pa[0] = pa[1] = make_float4(0.f, 0.f, 0.f, 0.f);
        if (gi1 >= 0) {
            const float4* src = (const float4*)(feat + (size_t)gi1 * CHUNK) + aseg * 2;
            pa[2] = __ldg(src + 0); pa[3] = __ldg(src + 1);
        } else pa[2] = pa[3] = make_float4(0.f, 0.f, 0.f, 0.f);
    };
    auto a_store = [&](int buf) {
        const int sw = arow & 7;
        #pragma unroll
        for (int u = 0; u < 2; ++u) {     // u: chunk half (unit aseg vs 8+aseg)
            float4 v0 = pa[2 * u], v1 = pa[2 * u + 1];
            uint4 h;
            h.x = pack_h2(v0.x, v0.y);
            h.y = pack_h2(v0.z, v0.w);
            h.z = pack_h2(v1.x, v1.y);
            h.w = pack_h2(v1.z, v1.w);
            const int unit = u * 8 + aseg;
            const int o = arow * 256 + ((unit ^ sw) << 4);
            *(uint4*)(sm + SM_A + buf * ATB + o) = h;
        }
    };
    auto b_issue = [&](int s, int buf) {
        const int c0 = 2 * s;
        const int nk = (2 * s + 1 < K3) ? 8 : 4;     // 16B lines per thread
        const char* srcB = (const char*)g_w + (size_t)c0 * 16384;
        uint32_t dB = smb + SM_B + buf * BTB;
        for (int j = 0; j < nk; ++j) {
            int idx  = tid + j * NTH;
            int krow = idx >> 4;
            int col  = idx & 15;
            int dof  = krow * 256 + ((col ^ (krow & 7)) << 4);
            int so   = krow * 256 + col * 16;
            cpasync16(dB + dof, srcB + so);
        }
    };

    // -------- compute (per warp: m16 x n32) --------
    const int mw = wid & 1, nw = wid >> 1;   // 2 m-warps x 4 n-warps
    const int m0 = mw * 16;
    float acc[4][4];
    #pragma unroll
    for (int t = 0; t < 4; ++t)
        #pragma unroll
        for (int q = 0; q < 4; ++q) acc[t][q] = 0.f;

    const int a_r  = m0 + (lane & 15);
    const int a_hi = (lane >> 4);
    const int k_l  = (lane & 15);

    auto mma_stage = [&](int buf) {
        const uint32_t aB = smb + SM_A + buf * ATB + a_r * 256;
        const uint32_t bB = smb + SM_B + buf * BTB;
        const int asw = (a_r & 7);
        #pragma unroll
        for (int ks = 0; ks < 8; ++ks) {
            uint32_t ah[4];
            const int acol = ks * 2 + a_hi;
            ldsm4(ah, aB + (uint32_t)((acol ^ asw) << 4));
            const int krow = ks * 16 + k_l;
            const uint32_t brow = (uint32_t)(krow * 256);
            const int ksw = (krow & 7);
            #pragma unroll
            for (int tt = 0; tt < 2; ++tt) {
                uint32_t bh[4];
                const int bcol = nw * 4 + tt * 2 + a_hi;
                ldsm4t(bh, brow + bB + (uint32_t)((bcol ^ ksw) << 4));
                mma16816(acc[2 * tt],     ah, bh[0], bh[1]);
                mma16816(acc[2 * tt + 1], ah, bh[2], bh[3]);
            }
        }
    };

    // -------- pipelined main loop (double-buffered stages) --------
    b_issue(0, 0);
    a_issue(0);
    a_store(0);
    cpwait_all();
    __syncthreads();

    for (int s = 0; s < stages; ++s) {
        const int buf = s & 1;
        const bool nxt = (s + 1) < stages;
        if (nxt) { b_issue(s + 1, buf ^ 1); a_issue(s + 1); }
        mma_stage(buf);
        if (nxt) a_store(buf ^ 1);
        cpwait_all();
        __syncthreads();
    }

    // -------- unscale (W was x2^14) --------
    #pragma unroll
    for (int t = 0; t < 4; ++t)
        #pragma unroll
        for (int q = 0; q < 4; ++q) acc[t][q] *= WINV;

    // -------- LayerNorm epilogue --------
    {
        float s0 = 0.f, q0 = 0.f, s1 = 0.f, q1 = 0.f;
        #pragma unroll
        for (int t = 0; t < 4; ++t) {
            s0 += acc[t][0] + acc[t][1];
            q0 += acc[t][0] * acc[t][0] + acc[t][1] * acc[t][1];
            s1 += acc[t][2] + acc[t][3];
            q1 += acc[t][2] * acc[t][2] + acc[t][3] * acc[t][3];
        }
        #pragma unroll
        for (int d = 1; d <= 2; d <<= 1) {
            s0 += __shfl_xor_sync(0xffffffffu, s0, d);
            q0 += __shfl_xor_sync(0xffffffffu, q0, d);
            s1 += __shfl_xor_sync(0xffffffffu, s1, d);
            q1 += __shfl_xor_sync(0xffffffffu, q1, d);
        }
        if ((lane & 3) == 0) {
            int r0 = m0 + (lane >> 2);
            s_red[r0 * 8 + nw * 2 + 0] = s0;
            s_red[r0 * 8 + nw * 2 + 1] = q0;
            s_red[(r0 + 8) * 8 + nw * 2 + 0] = s1;
            s_red[(r0 + 8) * 8 + nw * 2 + 1] = q1;
        }
    }
    __syncthreads();

    {
        const int r0 = m0 + (lane >> 2);
        const int r1 = r0 + 8;
        const float invC = 1.0f / 128.0f;
        float sA = s_red[r0 * 8 + 0] + s_red[r0 * 8 + 2] + s_red[r0 * 8 + 4] + s_red[r0 * 8 + 6];
        float qA = s_red[r0 * 8 + 1] + s_red[r0 * 8 + 3] + s_red[r0 * 8 + 5] + s_red[r0 * 8 + 7];
        float sB = s_red[r1 * 8 + 0] + s_red[r1 * 8 + 2] + s_red[r1 * 8 + 4] + s_red[r1 * 8 + 6];
        float qB = s_red[r1 * 8 + 1] + s_red[r1 * 8 + 3] + s_red[r1 * 8 + 5] + s_red[r1 * 8 + 7];
        float muA = sA * invC, muB = sB * invC;
        float ivA = rsqrtf(fmaxf(qA * invC - muA * muA, 0.f) + 1e-3f);
        float ivB = rsqrtf(fmaxf(qB * invC - muB * muB, 0.f) + 1e-3f);
        const int gr0 = row0 + r0, gr1 = row0 + r1;
        const bool vA = (gr0 < rows_total) && s_val[r0];
        const bool vB = (gr1 < rows_total) && s_val[r1];
        #pragma unroll
        for (int t = 0; t < 4; ++t) {
            const int c = nw * 32 + (t >> 1) * 16 + (t & 1) * 8 + (lane & 3) * 2;
            const float g0 = s_gb[c], g1 = s_gb[c + 1];
            const float b0 = s_gb[128 + c], b1 = s_gb[128 + c + 1];
            if (gr0 < rows_total) {
                float2 o = make_float2(0.f, 0.f);
                if (vA) {
                    o.x = fmaxf((acc[t][0] - muA) * ivA * g0 + b0, 0.f);
                    o.y = fmaxf((acc[t][1] - muA) * ivA * g1 + b1, 0.f);
                }
                *(float2*)(out_feat + (size_t)gr0 * 128 + c) = o;
            }
            if (gr1 < rows_total) {
                float2 o = make_float2(0.f, 0.f);
                if (vB) {
                    o.x = fmaxf((acc[t][2] - muB) * ivB * g0 + b0, 0.f);
                    o.y = fmaxf((acc[t][3] - muB) * ivB * g1 + b1, 0.f);
                }
                *(float2*)(out_feat + (size_t)gr1 * 128 + c) = o;
            }
        }
    }

    // -------- coords --------
    if (tid < TILE_M) {
        int r = row0 + tid;
        if (r < rows_total) {
            int b = r / K;
            float col0 = (b < B - 1) ? (float)(b + 1) : 0.f;
            float x = 0.f, y = 0.f, z = 0.f;
            if (s_val[tid]) {
                int src = s_src[tid];
                x = coors[src * 3 + 0];
                y = coors[src * 3 + 1];
                z = coors[src * 3 + 2];
            }
            ((float4*)out_coor)[r] = make_float4(col0, x, y, z);
        }
    }
}

extern "C" void kernel_launch(void* const* d_in, const int* in_sizes, int n_in,
                              void* d_out, int out_size) {
    const float* feat     = (const float*)d_in[0];
    const float* coors    = (const float*)d_in[1];
    const int*   vidx     = (const int*)d_in[2];
    const int*   num_list = (const int*)d_in[3];
    const float* W        = (const float*)d_in[4];
    const float* gamma    = (const float*)d_in[5];
    const float* beta     = (const float*)d_in[6];

    int B    = in_sizes[3];
    int Cout = in_sizes[5];                 // 128
    int M    = in_sizes[1] / 3;
    int K3   = in_sizes[2] / M;             // 27
    int Cin  = (in_sizes[4] / Cout) / K3;   // 64
    int N    = in_sizes[0] / Cin;
    int Ktot = K3 * Cin;

    int rows_total = out_size / (Cout + 4); // B*K
    int K = rows_total / B;

    float* out_feat = (float*)d_out;
    float* out_coor = out_feat + (size_t)rows_total * Cout;

    int total8 = (Ktot * Cout) / 8;
    prep_w<<<(total8 + 255) / 256, 256>>>(W, total8);

    cudaFuncSetAttribute(fused_mma_kernel,
                         cudaFuncAttributeMaxDynamicSharedMemorySize, SM_TOTAL);
    int grid = (rows_total + TILE_M - 1) / TILE_M;
    fused_mma_kernel<<<grid, NTH, SM_TOTAL>>>(feat, coors, vidx, num_list, gamma, beta,
                                              out_feat, out_coor,
                                              N, M, K3, B, K, rows_total);
}

// round 17
// speedup vs baseline: 1.4556x; 1.4556x over previous
#include <cuda_runtime.h>
#include <cuda_fp16.h>
#include <cstdint>

// DynamicPointConvBackBone via mma.sync (base-ISA HMMA; tcgen05 unavailable on
// the harness's compute_103 PTX target).
// Resample-first: only B*K rows computed. GEMM [8192 x 1728] @ [1728 x 128]
// in single-pass fp16 (W pre-scaled by 2^14; accumulators unscaled before LN),
// fp32 accumulate. LayerNorm(eps=1e-3)+ReLU epilogue + coords output.
// R16 = R8 GEMM kernel (best known, 30.8us) UNCHANGED + vectorized prep_w
// (float4 -> uint4, 8 elems/thread) cutting the 4.8us serial prep head.

#define TILE_M 32
#define NTH    256
#define IDXP   28
#define MAXCH  28
#define CHUNK  64        // = Cin
#define ATB    4096      // A tile bytes (32 rows x 64 fp16 x 2B)
#define BTB    16384     // B tile bytes (64 k x 128 n x 2B)
#define WSCALE 16384.0f
#define WINV   (1.0f / 16384.0f)

// dynamic smem layout
#define SM_A   0
#define SM_B   (SM_A + 2 * ATB)              // 8192
#define SM_IDX (SM_B + 2 * BTB)              // 40960
#define SM_SRC (SM_IDX + TILE_M * IDXP * 4)  // 44544
#define SM_VAL (SM_SRC + TILE_M * 4)         // 44672
#define SM_RED (SM_VAL + 32)                 // 44704 (32 rows x 4 nwarps x 2)
#define SM_GB  (SM_RED + TILE_M * 8 * 4)     // 45728 (gamma 128 + beta 128)
#define SM_TOTAL (SM_GB + 256 * 4)           // 46752

__device__ __align__(16) __half g_w[MAXCH * CHUNK * 128];   // [k][n] fp16, x2^14

static __device__ __forceinline__ uint32_t smem_u32(const void* p) {
    uint32_t a;
    asm("{ .reg .u64 t; cvta.to.shared.u64 t, %1; cvt.u32.u64 %0, t; }" : "=r"(a) : "l"(p));
    return a;
}
static __device__ __forceinline__ uint32_t pack_h2(float lo, float hi) {
    uint32_t r;
    asm("cvt.rn.f16x2.f32 %0, %1, %2;" : "=r"(r) : "f"(hi), "f"(lo));
    return r;
}
static __device__ __forceinline__ void cpasync16(uint32_t dst, const void* src) {
    asm volatile("cp.async.cg.shared.global [%0], [%1], 16;" :: "r"(dst), "l"(src) : "memory");
}
static __device__ __forceinline__ void cpwait_all() {
    asm volatile("cp.async.wait_all;" ::: "memory");
}
static __device__ __forceinline__ void ldsm4(uint32_t* r, uint32_t addr) {
    asm volatile("ldmatrix.sync.aligned.m8n8.x4.shared.b16 {%0,%1,%2,%3}, [%4];"
                 : "=r"(r[0]), "=r"(r[1]), "=r"(r[2]), "=r"(r[3]) : "r"(addr));
}
static __device__ __forceinline__ void ldsm4t(uint32_t* r, uint32_t addr) {
    asm volatile("ldmatrix.sync.aligned.m8n8.x4.trans.shared.b16 {%0,%1,%2,%3}, [%4];"
                 : "=r"(r[0]), "=r"(r[1]), "=r"(r[2]), "=r"(r[3]) : "r"(addr));
}
static __device__ __forceinline__ void mma16816(float* d, const uint32_t* a,
                                                uint32_t b0, uint32_t b1) {
    asm volatile(
        "mma.sync.aligned.m16n8k16.row.col.f32.f16.f16.f32 "
        "{%0,%1,%2,%3}, {%4,%5,%6,%7}, {%8,%9}, {%0,%1,%2,%3};"
        : "+f"(d[0]), "+f"(d[1]), "+f"(d[2]), "+f"(d[3])
        : "r"(a[0]), "r"(a[1]), "r"(a[2]), "r"(a[3]), "r"(b0), "r"(b1));
}

// ---------------- prep: W -> fp16 x2^14, [k][n], 8 elems/thread ----------------
__global__ void prep_w(const float* __restrict__ W, int total8) {
    int t = blockIdx.x * blockDim.x + threadIdx.x;
    if (t >= total8) return;
    float4 v0 = __ldg((const float4*)W + 2 * t);
    float4 v1 = __ldg((const float4*)W + 2 * t + 1);
    uint4 h;
    h.x = pack_h2(v0.x * WSCALE, v0.y * WSCALE);
    h.y = pack_h2(v0.z * WSCALE, v0.w * WSCALE);
    h.z = pack_h2(v1.x * WSCALE, v1.y * WSCALE);
    h.w = pack_h2(v1.z * WSCALE, v1.w * WSCALE);
    ((uint4*)g_w)[t] = h;
}

// ---------------- main fused kernel (byte-identical logic to R8) ----------------
__global__ __launch_bounds__(NTH, 2)
void fused_mma_kernel(
    const float* __restrict__ feat,   // [N, 64]
    const float* __restrict__ coors,  // [M, 3]
    const int*   __restrict__ vidx,   // [M, K3]
    const int*   __restrict__ nums,   // [B]
    const float* __restrict__ gamma,  // [128]
    const float* __restrict__ beta,   // [128]
    float* __restrict__ out_feat,     // [rows_total, 128]
    float* __restrict__ out_coor,     // [rows_total, 4]
    int N, int M, int K3, int B, int K, int rows_total)
{
    extern __shared__ __align__(128) char sm[];
    const uint32_t smb = smem_u32(sm);
    const int tid  = threadIdx.x;
    const int wid  = tid >> 5;
    const int lane = tid & 31;
    const int row0 = blockIdx.x * TILE_M;

    int* s_idx = (int*)(sm + SM_IDX);
    int* s_src = (int*)(sm + SM_SRC);
    unsigned char* s_val = (unsigned char*)(sm + SM_VAL);
    float* s_red = (float*)(sm + SM_RED);
    float* s_gb  = (float*)(sm + SM_GB);

    // per-row source & validity
    if (tid < TILE_M) {
        int r = row0 + tid;
        int src = 0; bool valid = false;
        if (r < rows_total) {
            int b = r / K;
            int j = r - b * K;
            int off = 0;
            for (int i = 0; i < b; ++i) off += nums[i];
            valid = j < min(nums[b], K);
            src   = max(0, min(off + j, M - 1));
        }
        s_src[tid] = src;
        s_val[tid] = valid ? 1 : 0;
    }
    if (tid >= 128) {
        s_gb[tid - 128] = gamma[tid - 128];
        s_gb[tid]       = beta[tid - 128];
    }
    __syncthreads();

    // neighbor indices for this row tile
    for (int i = tid; i < TILE_M * K3; i += NTH) {
        int rr = i / K3, cc = i - rr * K3;
        int v = vidx[(long long)s_src[rr] * K3 + cc];
        s_idx[rr * IDXP + cc] = (v < 0) ? -1 : min(v, N - 1);
    }
    __syncthreads();

    // -------- loader helpers --------
    const int arow = tid >> 3;          // gather row 0..31
    const int aseg = tid & 7;           // 32B segment of 256B fp32 feature row
    float4 pa0, pa1;

    auto a_issue = [&](int c) {
        int gi = s_idx[arow * IDXP + c];
        if (gi >= 0) {
            const float4* src = (const float4*)(feat + (size_t)gi * CHUNK) + aseg * 2;
            pa0 = __ldg(src + 0);
            pa1 = __ldg(src + 1);
        } else {
            pa0 = pa1 = make_float4(0.f, 0.f, 0.f, 0.f);
        }
    };
    auto a_store = [&](int buf) {
        uint4 h;
        h.x = pack_h2(pa0.x, pa0.y);
        h.y = pack_h2(pa0.z, pa0.w);
        h.z = pack_h2(pa1.x, pa1.y);
        h.w = pack_h2(pa1.z, pa1.w);
        const int o = arow * 128 + ((aseg ^ (arow & 7)) << 4);
        *(uint4*)(sm + SM_A + buf * ATB + o) = h;
    };
    auto b_issue = [&](int c, int buf) {
        const char* srcB = (const char*)g_w + (size_t)c * BTB;
        uint32_t dB = smb + SM_B + buf * BTB;
        #pragma unroll
        for (int j = 0; j < 4; ++j) {
            int idx  = tid + j * NTH;
            int krow = idx >> 4;
            int col  = idx & 15;
            int dof  = krow * 256 + ((col ^ (krow & 7)) << 4);
            int so   = krow * 256 + col * 16;
            cpasync16(dB + dof, srcB + so);
        }
    };

    // -------- compute (per warp: m16 x n32) --------
    const int mw = wid & 1, nw = wid >> 1;   // 2 m-warps x 4 n-warps
    const int m0 = mw * 16;
    float acc[4][4];
    #pragma unroll
    for (int t = 0; t < 4; ++t)
        #pragma unroll
        for (int q = 0; q < 4; ++q) acc[t][q] = 0.f;

    const int a_r  = m0 + (lane & 15);
    const int a_hi = (lane >> 4);
    const int k_l  = (lane & 15);

    auto mma_chunk = [&](int buf) {
        const uint32_t aB = smb + SM_A + buf * ATB + a_r * 128;
        const uint32_t bB = smb + SM_B + buf * BTB;
        const int asw = (a_r & 7);
        #pragma unroll
        for (int ks = 0; ks < 4; ++ks) {
            uint32_t ah[4];
            const int acol = ks * 2 + a_hi;
            ldsm4(ah, aB + (uint32_t)((acol ^ asw) << 4));
            const int krow = ks * 16 + k_l;
            const uint32_t brow = (uint32_t)(krow * 256);
            const int ksw = (krow & 7);
            #pragma unroll
            for (int tt = 0; tt < 2; ++tt) {
                uint32_t bh[4];
                const int bcol = nw * 4 + tt * 2 + a_hi;
                ldsm4t(bh, brow + bB + (uint32_t)((bcol ^ ksw) << 4));
                mma16816(acc[2 * tt],     ah, bh[0], bh[1]);
                mma16816(acc[2 * tt + 1], ah, bh[2], bh[3]);
            }
        }
    };

    // -------- pipelined main loop --------
    b_issue(0, 0);
    a_issue(0);
    a_store(0);
    cpwait_all();
    __syncthreads();

    for (int c = 0; c < K3; ++c) {
        const int buf = c & 1;
        const bool nxt = (c + 1) < K3;
        if (nxt) { b_issue(c + 1, buf ^ 1); a_issue(c + 1); }
        mma_chunk(buf);
        if (nxt) a_store(buf ^ 1);
        cpwait_all();
        __syncthreads();
    }

    // -------- unscale (W was x2^14) --------
    #pragma unroll
    for (int t = 0; t < 4; ++t)
        #pragma unroll
        for (int q = 0; q < 4; ++q) acc[t][q] *= WINV;

    // -------- LayerNorm epilogue --------
    {
        float s0 = 0.f, q0 = 0.f, s1 = 0.f, q1 = 0.f;
        #pragma unroll
        for (int t = 0; t < 4; ++t) {
            s0 += acc[t][0] + acc[t][1];
            q0 += acc[t][0] * acc[t][0] + acc[t][1] * acc[t][1];
            s1 += acc[t][2] + acc[t][3];
            q1 += acc[t][2] * acc[t][2] + acc[t][3] * acc[t][3];
        }
        #pragma unroll
        for (int m = 1; m <= 2; m <<= 1) {
            s0 += __shfl_xor_sync(0xffffffffu, s0, m);
            q0 += __shfl_xor_sync(0xffffffffu, q0, m);
            s1 += __shfl_xor_sync(0xffffffffu, s1, m);
            q1 += __shfl_xor_sync(0xffffffffu, q1, m);
        }
        if ((lane & 3) == 0) {
            int r0 = m0 + (lane >> 2);
            s_red[r0 * 8 + nw * 2 + 0] = s0;
            s_red[r0 * 8 + nw * 2 + 1] = q0;
            s_red[(r0 + 8) * 8 + nw * 2 + 0] = s1;
            s_red[(r0 + 8) * 8 + nw * 2 + 1] = q1;
        }
    }
    __syncthreads();

    {
        const int r0 = m0 + (lane >> 2);
        const int r1 = r0 + 8;
        const float invC = 1.0f / 128.0f;
        float sA = s_red[r0 * 8 + 0] + s_red[r0 * 8 + 2] + s_red[r0 * 8 + 4] + s_red[r0 * 8 + 6];
        float qA = s_red[r0 * 8 + 1] + s_red[r0 * 8 + 3] + s_red[r0 * 8 + 5] + s_red[r0 * 8 + 7];
        float sB = s_red[r1 * 8 + 0] + s_red[r1 * 8 + 2] + s_red[r1 * 8 + 4] + s_red[r1 * 8 + 6];
        float qB = s_red[r1 * 8 + 1] + s_red[r1 * 8 + 3] + s_red[r1 * 8 + 5] + s_red[r1 * 8 + 7];
        float muA = sA * invC, muB = sB * invC;
        float ivA = rsqrtf(fmaxf(qA * invC - muA * muA, 0.f) + 1e-3f);
        float ivB = rsqrtf(fmaxf(qB * invC - muB * muB, 0.f) + 1e-3f);
        const int gr0 = row0 + r0, gr1 = row0 + r1;
        const bool vA = (gr0 < rows_total) && s_val[r0];
        const bool vB = (gr1 < rows_total) && s_val[r1];
        #pragma unroll
        for (int t = 0; t < 4; ++t) {
            const int c = nw * 32 + (t >> 1) * 16 + (t & 1) * 8 + (lane & 3) * 2;
            const float g0 = s_gb[c], g1 = s_gb[c + 1];
            const float b0 = s_gb[128 + c], b1 = s_gb[128 + c + 1];
            if (gr0 < rows_total) {
                float2 o = make_float2(0.f, 0.f);
                if (vA) {
                    o.x = fmaxf((acc[t][0] - muA) * ivA * g0 + b0, 0.f);
                    o.y = fmaxf((acc[t][1] - muA) * ivA * g1 + b1, 0.f);
                }
                *(float2*)(out_feat + (size_t)gr0 * 128 + c) = o;
            }
            if (gr1 < rows_total) {
                float2 o = make_float2(0.f, 0.f);
                if (vB) {
                    o.x = fmaxf((acc[t][2] - muB) * ivB * g0 + b0, 0.f);
                    o.y = fmaxf((acc[t][3] - muB) * ivB * g1 + b1, 0.f);
                }
                *(float2*)(out_feat + (size_t)gr1 * 128 + c) = o;
            }
        }
    }

    // -------- coords --------
    if (tid < TILE_M) {
        int r = row0 + tid;
        if (r < rows_total) {
            int b = r / K;
            float col0 = (b < B - 1) ? (float)(b + 1) : 0.f;
            float x = 0.f, y = 0.f, z = 0.f;
            if (s_val[tid]) {
                int src = s_src[tid];
                x = coors[src * 3 + 0];
                y = coors[src * 3 + 1];
                z = coors[src * 3 + 2];
            }
            ((float4*)out_coor)[r] = make_float4(col0, x, y, z);
        }
    }
}

extern "C" void kernel_launch(void* const* d_in, const int* in_sizes, int n_in,
                              void* d_out, int out_size) {
    const float* feat     = (const float*)d_in[0];
    const float* coors    = (const float*)d_in[1];
    const int*   vidx     = (const int*)d_in[2];
    const int*   num_list = (const int*)d_in[3];
    const float* W        = (const float*)d_in[4];
    const float* gamma    = (const float*)d_in[5];
    const float* beta     = (const float*)d_in[6];

    int B    = in_sizes[3];
    int Cout = in_sizes[5];                 // 128
    int M    = in_sizes[1] / 3;
    int K3   = in_sizes[2] / M;             // 27
    int Cin  = (in_sizes[4] / Cout) / K3;   // 64
    int N    = in_sizes[0] / Cin;
    int Ktot = K3 * Cin;

    int rows_total = out_size / (Cout + 4); // B*K
    int K = rows_total / B;

    float* out_feat = (float*)d_out;
    float* out_coor = out_feat + (size_t)rows_total * Cout;

    int total8 = (Ktot * Cout) / 8;
    prep_w<<<(total8 + 255) / 256, 256>>>(W, total8);

    cudaFuncSetAttribute(fused_mma_kernel,
                         cudaFuncAttributeMaxDynamicSharedMemorySize, SM_TOTAL);
    int grid = (rows_total + TILE_M - 1) / TILE_M;
    fused_mma_kernel<<<grid, NTH, SM_TOTAL>>>(feat, coors, vidx, num_list, gamma, beta,
                                              out_feat, out_coor,
                                              N, M, K3, B, K, rows_total);
}